// round 11
// baseline (speedup 1.0000x reference)
#include <cuda_runtime.h>
#include <cuda_fp16.h>
#include <math.h>
#include <stdint.h>

#define B_  2
#define N_  1024
#define D_  1024
#define R_  16
#define H_  2048
#define T_  (B_*N_)
#define G3_ (3*D_)
#define DR_ (D_*R_)

// ---------------- scratch ----------------
__device__ float g_xp[(size_t)T_*G3_];
__device__ float g_hbuf[2][B_*D_];
__device__ float g_gruout[(size_t)T_*D_];
__device__ float g_beta[T_];
__device__ float g_gated[(size_t)T_*D_];
__device__ float g_hid[(size_t)T_*H_];
__device__ float g_V2[R_*H_];
__device__ float g_c2[R_];
__device__ float g_s[T_*R_];
__device__ __half g_w2h[(size_t)DR_*H_];
__device__ __half g_w1h[(size_t)H_*D_];
__device__ __half g_gatedh[(size_t)T_*D_];
__device__ __half g_hidh[(size_t)T_*H_];

#define GCTAS 128
__device__ int g_arrive[GCTAS];
__device__ int g_gen;

// ---------------- helpers ----------------
__device__ __forceinline__ void fma2(unsigned long long &d, unsigned long long a, unsigned long long b){
    asm("fma.rn.f32x2 %0, %1, %2, %0;" : "+l"(d) : "l"(a), "l"(b));
}
__device__ __forceinline__ unsigned long long dup2(float x){
    unsigned long long r; unsigned int xi = __float_as_uint(x);
    asm("mov.b64 %0, {%1, %2};" : "=l"(r) : "r"(xi), "r"(xi));
    return r;
}
__device__ __forceinline__ unsigned long long pk2(float a, float b){
    unsigned long long r;
    asm("mov.b64 %0, {%1, %2};" : "=l"(r) : "r"(__float_as_uint(a)), "r"(__float_as_uint(b)));
    return r;
}
__device__ __forceinline__ float2 un2(unsigned long long v){
    unsigned int lo, hi;
    asm("mov.b64 {%0, %1}, %2;" : "=r"(lo), "=r"(hi) : "l"(v));
    return make_float2(__uint_as_float(lo), __uint_as_float(hi));
}
__device__ __forceinline__ float4 ldcg4(const float* p){
    float4 v;
    asm volatile("ld.global.cg.v4.f32 {%0,%1,%2,%3}, [%4];"
                 : "=f"(v.x),"=f"(v.y),"=f"(v.z),"=f"(v.w) : "l"(p));
    return v;
}
__device__ __forceinline__ int4 ldvol4(const int* p){
    int4 v;
    asm volatile("ld.volatile.global.v4.s32 {%0,%1,%2,%3}, [%4];"
                 : "=r"(v.x),"=r"(v.y),"=r"(v.z),"=r"(v.w) : "l"(p));
    return v;
}
__device__ __forceinline__ uint32_t s2u(const void* p){
    return (uint32_t)__cvta_generic_to_shared(p);
}
__device__ __forceinline__ float gelu_tanh(float x){
    float c = x + 0.044715f * x * x * x;
    return 0.5f * x * (1.0f + tanhf(0.7978845608028654f * c));
}
__device__ __forceinline__ float sigm(float x){ return 1.0f / (1.0f + expf(-x)); }
// fast, overflow-safe variants for the recurrence hot path (MUFU-based)
__device__ __forceinline__ float sigm_fast(float x){ return 1.0f / (1.0f + __expf(-x)); }
__device__ __forceinline__ float tanh_fast(float x){ return 1.0f - 2.0f / (__expf(2.0f*x) + 1.0f); }

// ---------------- fp32->fp16 convert ----------------
__global__ void conv_half(const float* __restrict__ src, __half* __restrict__ dst, size_t n){
    size_t i = ((size_t)blockIdx.x*256 + threadIdx.x)*8;
    if (i >= n) return;
    float4 v0 = *(const float4*)&src[i];
    float4 v1 = *(const float4*)&src[i+4];
    __half2 h0 = __floats2half2_rn(v0.x, v0.y);
    __half2 h1 = __floats2half2_rn(v0.z, v0.w);
    __half2 h2 = __floats2half2_rn(v1.x, v1.y);
    __half2 h3 = __floats2half2_rn(v1.z, v1.w);
    uint4 o;
    o.x = *(uint32_t*)&h0; o.y = *(uint32_t*)&h1; o.z = *(uint32_t*)&h2; o.w = *(uint32_t*)&h3;
    *(uint4*)&dst[i] = o;
}

// ---------------- fp32 SGEMM NT (xp only): C = A@Bw^T + bias ----------------
#define BM 128
#define BN 128
#define BK 16
#define SPAD 4

__global__ __launch_bounds__(256) void sgemm_bias(
    const float* __restrict__ A, const float* __restrict__ Bw,
    const float* __restrict__ bias, float* __restrict__ C,
    int M, int N, int K)
{
    __shared__ float As[2][BK][BM + SPAD];
    __shared__ float Bs[2][BK][BN + SPAD];

    const int tid = threadIdx.x;
    const int bn  = blockIdx.x, bm = blockIdx.y;
    const int tr  = tid >> 4, tc = tid & 15;
    const float* Ab = A  + (size_t)bm * BM * K;
    const float* Bb = Bw + (size_t)bn * BN * K;
    const int lr0 = tid >> 2;
    const int lc0 = (tid & 3) * 4;

    unsigned long long acc[8][4];
    #pragma unroll
    for (int i = 0; i < 8; i++)
        #pragma unroll
        for (int j = 0; j < 4; j++) acc[i][j] = 0ull;

    const int KT = K / BK;
    float4 ta0 = *(const float4*)&Ab[(size_t)lr0      * K + lc0];
    float4 ta1 = *(const float4*)&Ab[(size_t)(lr0+64) * K + lc0];
    float4 tb0 = *(const float4*)&Bb[(size_t)lr0      * K + lc0];
    float4 tb1 = *(const float4*)&Bb[(size_t)(lr0+64) * K + lc0];
    As[0][lc0+0][lr0]=ta0.x; As[0][lc0+1][lr0]=ta0.y; As[0][lc0+2][lr0]=ta0.z; As[0][lc0+3][lr0]=ta0.w;
    As[0][lc0+0][lr0+64]=ta1.x; As[0][lc0+1][lr0+64]=ta1.y; As[0][lc0+2][lr0+64]=ta1.z; As[0][lc0+3][lr0+64]=ta1.w;
    Bs[0][lc0+0][lr0]=tb0.x; Bs[0][lc0+1][lr0]=tb0.y; Bs[0][lc0+2][lr0]=tb0.z; Bs[0][lc0+3][lr0]=tb0.w;
    Bs[0][lc0+0][lr0+64]=tb1.x; Bs[0][lc0+1][lr0+64]=tb1.y; Bs[0][lc0+2][lr0+64]=tb1.z; Bs[0][lc0+3][lr0+64]=tb1.w;
    __syncthreads();

    int buf = 0;
    for (int kt = 0; kt < KT; kt++){
        if (kt + 1 < KT){
            const float* An = Ab + (size_t)(kt+1) * BK;
            const float* Bn = Bb + (size_t)(kt+1) * BK;
            ta0 = *(const float4*)&An[(size_t)lr0      * K + lc0];
            ta1 = *(const float4*)&An[(size_t)(lr0+64) * K + lc0];
            tb0 = *(const float4*)&Bn[(size_t)lr0      * K + lc0];
            tb1 = *(const float4*)&Bn[(size_t)(lr0+64) * K + lc0];
        }
        #pragma unroll
        for (int k = 0; k < BK; k++){
            float4 av0 = *(float4*)&As[buf][k][tr*8];
            float4 av1 = *(float4*)&As[buf][k][tr*8 + 4];
            ulonglong2 bv0 = *(ulonglong2*)&Bs[buf][k][tc*8];
            ulonglong2 bv1 = *(ulonglong2*)&Bs[buf][k][tc*8 + 4];
            unsigned long long ad[8];
            ad[0]=dup2(av0.x); ad[1]=dup2(av0.y); ad[2]=dup2(av0.z); ad[3]=dup2(av0.w);
            ad[4]=dup2(av1.x); ad[5]=dup2(av1.y); ad[6]=dup2(av1.z); ad[7]=dup2(av1.w);
            #pragma unroll
            for (int i = 0; i < 8; i++){
                fma2(acc[i][0], ad[i], bv0.x);
                fma2(acc[i][1], ad[i], bv0.y);
                fma2(acc[i][2], ad[i], bv1.x);
                fma2(acc[i][3], ad[i], bv1.y);
            }
        }
        if (kt + 1 < KT){
            buf ^= 1;
            As[buf][lc0+0][lr0]=ta0.x; As[buf][lc0+1][lr0]=ta0.y; As[buf][lc0+2][lr0]=ta0.z; As[buf][lc0+3][lr0]=ta0.w;
            As[buf][lc0+0][lr0+64]=ta1.x; As[buf][lc0+1][lr0+64]=ta1.y; As[buf][lc0+2][lr0+64]=ta1.z; As[buf][lc0+3][lr0+64]=ta1.w;
            Bs[buf][lc0+0][lr0]=tb0.x; Bs[buf][lc0+1][lr0]=tb0.y; Bs[buf][lc0+2][lr0]=tb0.z; Bs[buf][lc0+3][lr0]=tb0.w;
            Bs[buf][lc0+0][lr0+64]=tb1.x; Bs[buf][lc0+1][lr0+64]=tb1.y; Bs[buf][lc0+2][lr0+64]=tb1.z; Bs[buf][lc0+3][lr0+64]=tb1.w;
            __syncthreads();
        }
    }

    const int row0 = bm*BM + tr*8, col0 = bn*BN + tc*8;
    float bv[8];
    float4 q0 = *(const float4*)&bias[col0];
    float4 q1 = *(const float4*)&bias[col0 + 4];
    bv[0]=q0.x; bv[1]=q0.y; bv[2]=q0.z; bv[3]=q0.w;
    bv[4]=q1.x; bv[5]=q1.y; bv[6]=q1.z; bv[7]=q1.w;
    #pragma unroll
    for (int i = 0; i < 8; i++){
        float cv[8];
        #pragma unroll
        for (int j = 0; j < 4; j++){
            float2 p = un2(acc[i][j]);
            cv[2*j]   = p.x + bv[2*j];
            cv[2*j+1] = p.y + bv[2*j+1];
        }
        *(float4*)&C[(size_t)(row0+i)*N + col0]     = make_float4(cv[0],cv[1],cv[2],cv[3]);
        *(float4*)&C[(size_t)(row0+i)*N + col0 + 4] = make_float4(cv[4],cv[5],cv[6],cv[7]);
    }
}

// ---------------- fp16 HMMA GEMM NT ----------------
#define MBM 128
#define MBN 128
#define MBK 32
#define MROW 40

template<int EPI>
__global__ __launch_bounds__(256) void hgemm_nt(
    const __half* __restrict__ Ah, const __half* __restrict__ Bh,
    const float* __restrict__ bias, float* __restrict__ C,
    __half* __restrict__ Ch,
    int M, int N, int K,
    const float* __restrict__ latent, const float* __restrict__ gated)
{
    __shared__ __align__(16) __half At[MBM*MROW];
    __shared__ __align__(16) __half Bt[MBN*MROW];
    __shared__ float ss[(EPI==3)? MBM*16 : 1];

    const int tid  = threadIdx.x;
    const int bm   = blockIdx.x, bn = blockIdx.y;
    const int lane = tid & 31, w = tid >> 5;
    const int wm   = w >> 2, wn = w & 3;
    const int g    = lane >> 2, qt = lane & 3;

    if (EPI == 3){
        for (int k = tid; k < MBM*16; k += 256)
            ss[k] = g_s[(bm*MBM + (k >> 4))*R_ + (k & 15)];
    }

    const __half* Ab = Ah + (size_t)bm * MBM * K;
    const __half* Bb = Bh + (size_t)bn * MBN * K;

    const int crow = tid >> 1;
    const int cc   = (tid & 1) * 2;

    float acc[4][4][4];
    #pragma unroll
    for (int a = 0; a < 4; a++)
        #pragma unroll
        for (int b = 0; b < 4; b++)
            #pragma unroll
            for (int c = 0; c < 4; c++) acc[a][b][c] = 0.0f;

    const int KT = K / MBK;
    uint4 ra0, ra1, rb0, rb1;
    ra0 = *(const uint4*)(Ab + (size_t)crow*K + cc*8);
    ra1 = *(const uint4*)(Ab + (size_t)crow*K + cc*8 + 8);
    rb0 = *(const uint4*)(Bb + (size_t)crow*K + cc*8);
    rb1 = *(const uint4*)(Bb + (size_t)crow*K + cc*8 + 8);
    ((uint4*)At)[crow*5 + cc] = ra0; ((uint4*)At)[crow*5 + cc + 1] = ra1;
    ((uint4*)Bt)[crow*5 + cc] = rb0; ((uint4*)Bt)[crow*5 + cc + 1] = rb1;
    __syncthreads();

    const uint32_t aBase = s2u(At), bBase = s2u(Bt);

    for (int kt = 0; kt < KT; kt++){
        if (kt + 1 < KT){
            const __half* An = Ab + (size_t)(kt+1)*MBK;
            const __half* Bn = Bb + (size_t)(kt+1)*MBK;
            ra0 = *(const uint4*)(An + (size_t)crow*K + cc*8);
            ra1 = *(const uint4*)(An + (size_t)crow*K + cc*8 + 8);
            rb0 = *(const uint4*)(Bn + (size_t)crow*K + cc*8);
            rb1 = *(const uint4*)(Bn + (size_t)crow*K + cc*8 + 8);
        }
        #pragma unroll
        for (int ks = 0; ks < 2; ks++){
            uint32_t af[4][4];
            #pragma unroll
            for (int mt = 0; mt < 4; mt++){
                int r   = wm*64 + mt*16 + (lane & 15);
                int col = ks*16 + ((lane >> 4) << 3);
                uint32_t addr = aBase + (uint32_t)(r*MROW + col)*2;
                asm volatile("ldmatrix.sync.aligned.m8n8.x4.shared.b16 {%0,%1,%2,%3},[%4];"
                    : "=r"(af[mt][0]),"=r"(af[mt][1]),"=r"(af[mt][2]),"=r"(af[mt][3]) : "r"(addr));
            }
            uint32_t bf[2][4];
            #pragma unroll
            for (int np = 0; np < 2; np++){
                int r   = wn*32 + np*16 + (lane & 7) + ((lane & 16) ? 8 : 0);
                int col = ks*16 + ((lane & 8) ? 8 : 0);
                uint32_t addr = bBase + (uint32_t)(r*MROW + col)*2;
                asm volatile("ldmatrix.sync.aligned.m8n8.x4.shared.b16 {%0,%1,%2,%3},[%4];"
                    : "=r"(bf[np][0]),"=r"(bf[np][1]),"=r"(bf[np][2]),"=r"(bf[np][3]) : "r"(addr));
            }
            #pragma unroll
            for (int mt = 0; mt < 4; mt++)
                #pragma unroll
                for (int nt = 0; nt < 4; nt++){
                    uint32_t b0 = bf[nt>>1][(nt&1)*2], b1 = bf[nt>>1][(nt&1)*2 + 1];
                    asm volatile(
                        "mma.sync.aligned.m16n8k16.row.col.f32.f16.f16.f32 "
                        "{%0,%1,%2,%3},{%4,%5,%6,%7},{%8,%9},{%0,%1,%2,%3};"
                        : "+f"(acc[mt][nt][0]),"+f"(acc[mt][nt][1]),
                          "+f"(acc[mt][nt][2]),"+f"(acc[mt][nt][3])
                        : "r"(af[mt][0]),"r"(af[mt][1]),"r"(af[mt][2]),"r"(af[mt][3]),
                          "r"(b0),"r"(b1));
                }
        }
        __syncthreads();
        if (kt + 1 < KT){
            ((uint4*)At)[crow*5 + cc] = ra0; ((uint4*)At)[crow*5 + cc + 1] = ra1;
            ((uint4*)Bt)[crow*5 + cc] = rb0; ((uint4*)Bt)[crow*5 + cc + 1] = rb1;
            __syncthreads();
        }
    }

    if (EPI == 2){
        #pragma unroll
        for (int mt = 0; mt < 4; mt++)
            #pragma unroll
            for (int nt = 0; nt < 4; nt++)
                #pragma unroll
                for (int rh = 0; rh < 2; rh++){
                    int row = bm*MBM + wm*64 + mt*16 + g + rh*8;
                    int col = bn*MBN + wn*32 + nt*8 + qt*2;
                    float2 bv = *(const float2*)&bias[col];
                    float v0 = gelu_tanh(acc[mt][nt][rh*2+0] + bv.x);
                    float v1 = gelu_tanh(acc[mt][nt][rh*2+1] + bv.y);
                    *(float2*)&C[(size_t)row*N + col] = make_float2(v0, v1);
                    __half2 hv = __floats2half2_rn(v0, v1);
                    *(__half2*)&Ch[(size_t)row*N + col] = hv;
                }
    } else {
        #pragma unroll
        for (int mt = 0; mt < 4; mt++)
            #pragma unroll
            for (int rh = 0; rh < 2; rh++){
                int lrow = wm*64 + mt*16 + g + rh*8;
                int row  = bm*MBM + lrow;
                const float* sr = &ss[lrow*16];
                #pragma unroll
                for (int np = 0; np < 2; np++){
                    float p = 0.0f;
                    #pragma unroll
                    for (int sub = 0; sub < 2; sub++){
                        int nt   = np*2 + sub;
                        int colb = bn*MBN + wn*32 + nt*8 + qt*2;
                        float2 bv = *(const float2*)&bias[colb];
                        int rr = (nt & 1)*8 + qt*2;
                        p += (acc[mt][nt][rh*2+0] + bv.x)*sr[rr]
                           + (acc[mt][nt][rh*2+1] + bv.y)*sr[rr+1];
                    }
                    p += __shfl_xor_sync(0xffffffffu, p, 1);
                    p += __shfl_xor_sync(0xffffffffu, p, 2);
                    if (qt == 0){
                        int d = bn*8 + wn*2 + np;
                        size_t idx = (size_t)row*D_ + d;
                        C[idx] = latent[idx] + gated[idx]*p;
                    }
                }
            }
    }
}

// ---------------- GRU barrier reset (per launch, for graph replay) ----------------
__global__ void gru_reset(){
    if (threadIdx.x < GCTAS) g_arrive[threadIdx.x] = 0;
    if (threadIdx.x == 0) g_gen = 0;
}

// ---------------- persistent GRU: warp-per-dim compute, two-level barrier (proven) ----------------
__global__ __launch_bounds__(256) void gru_kernel(const float* __restrict__ w_hh, const float* __restrict__ b_hh)
{
    __shared__ float h_s[2*D_];

    const int tid = threadIdx.x, lane = tid & 31, warp = tid >> 5;
    const int bid = blockIdx.x;
    const int d0 = bid * 8;
    const int d  = d0 + warp;        // warp w owns dim d0+w (all 3 gates, both batches)

    // weights in registers: rows {0,1,2}*D + d
    unsigned long long wreg[3][16];
    float bh[3];
    #pragma unroll
    for (int q = 0; q < 3; q++){
        const float* wr = &w_hh[(size_t)(q*D_ + d) * D_];
        #pragma unroll
        for (int j = 0; j < 8; j++){
            float4 v = *(const float4*)&wr[lane*4 + j*128];
            wreg[q][2*j]   = pk2(v.x, v.y);
            wreg[q][2*j+1] = pk2(v.z, v.w);
        }
        bh[q] = b_hh[q*D_ + d];
    }

    // lane b (b<2) holds x gates + hprev for batch b of dim d
    float pxr = 0.f, pxz = 0.f, pxn = 0.f, hprev = 0.f;
    if (lane < 2){
        size_t xb = ((size_t)(lane*N_ + 0)) * G3_ + d;
        pxr = g_xp[xb]; pxz = g_xp[xb + D_]; pxn = g_xp[xb + 2*D_];
    }
    __syncthreads();

    int pbuf = 0;
    for (int t = 0; t < N_; t++){
        if (t > 0){
            // stage h (prev step) into smem; L2-only loads
            for (int k = tid*4; k < 2*D_; k += 1024)
                *(float4*)&h_s[k] = ldcg4(&g_hbuf[pbuf][k]);
        }
        __syncthreads();

        // ---- per-warp: 3 gate rows x 2 batches dot products + butterfly ----
        float s00=0.f,s01=0.f,s10=0.f,s11=0.f,s20=0.f,s21=0.f;
        if (t > 0){
            unsigned long long a00=0ull,a01=0ull,a10=0ull,a11=0ull,a20=0ull,a21=0ull;
            #pragma unroll
            for (int j = 0; j < 8; j++){
                ulonglong2 h0 = *(ulonglong2*)&h_s[lane*4 + j*128];
                ulonglong2 h1 = *(ulonglong2*)&h_s[D_ + lane*4 + j*128];
                fma2(a00, wreg[0][2*j], h0.x); fma2(a00, wreg[0][2*j+1], h0.y);
                fma2(a01, wreg[0][2*j], h1.x); fma2(a01, wreg[0][2*j+1], h1.y);
                fma2(a10, wreg[1][2*j], h0.x); fma2(a10, wreg[1][2*j+1], h0.y);
                fma2(a11, wreg[1][2*j], h1.x); fma2(a11, wreg[1][2*j+1], h1.y);
                fma2(a20, wreg[2][2*j], h0.x); fma2(a20, wreg[2][2*j+1], h0.y);
                fma2(a21, wreg[2][2*j], h1.x); fma2(a21, wreg[2][2*j+1], h1.y);
            }
            float2 p;
            p = un2(a00); s00 = p.x + p.y;
            p = un2(a01); s01 = p.x + p.y;
            p = un2(a10); s10 = p.x + p.y;
            p = un2(a11); s11 = p.x + p.y;
            p = un2(a20); s20 = p.x + p.y;
            p = un2(a21); s21 = p.x + p.y;
            #pragma unroll
            for (int o = 16; o > 0; o >>= 1){
                s00 += __shfl_xor_sync(0xffffffffu, s00, o);
                s01 += __shfl_xor_sync(0xffffffffu, s01, o);
                s10 += __shfl_xor_sync(0xffffffffu, s10, o);
                s11 += __shfl_xor_sync(0xffffffffu, s11, o);
                s20 += __shfl_xor_sync(0xffffffffu, s20, o);
                s21 += __shfl_xor_sync(0xffffffffu, s21, o);
            }
        }

        // ---- gates (lane b = batch b) + direct store; no hp_s staging ----
        if (lane < 2){
            float sr = lane ? s01 : s00;
            float sz = lane ? s11 : s10;
            float sn = lane ? s21 : s20;
            float r  = sigm_fast(pxr + sr + bh[0]);
            float z  = sigm_fast(pxz + sz + bh[1]);
            float ng = tanh_fast(pxn + r*(sn + bh[2]));
            float hnew = (1.0f - z)*ng + z*hprev;
            hprev = hnew;
            g_hbuf[pbuf ^ 1][lane*D_ + d] = hnew;
            g_gruout[((size_t)(lane*N_ + t)) * D_ + d] = hnew;
            __threadfence();   // publish h before arrival flag
        }
        __syncthreads();

        // --- two-level grid barrier (proven R6 design) ---
        if (tid == 0)
            ((volatile int*)g_arrive)[bid] = t + 1;
        // hide next step's x loads under the barrier
        if (lane < 2 && t + 1 < N_){
            size_t xb = ((size_t)(lane*N_ + t + 1)) * G3_ + d;
            pxr = g_xp[xb]; pxz = g_xp[xb + D_]; pxn = g_xp[xb + 2*D_];
        }
        if (bid == 0 && warp == 0){
            const int* fp = &g_arrive[lane * 4];
            for (;;){
                int4 f = ldvol4(fp);
                if (f.x > t && f.y > t && f.z > t && f.w > t) break;
            }
            __syncwarp();
            if (lane == 0){
                __threadfence();
                *(volatile int*)&g_gen = t + 1;
            }
        }
        if (bid != 0 && tid == 0){
            while (*(volatile int*)&g_gen <= t) { }
        }
        __syncthreads();
        pbuf ^= 1;
    }
}

// ---------------- beta ----------------
__global__ void beta_kernel(const float* __restrict__ beta_w){
    int gw = (blockIdx.x * blockDim.x + threadIdx.x) >> 5;
    int lane = threadIdx.x & 31;
    if (gw >= T_) return;
    const float* h = &g_gruout[(size_t)gw * D_];
    float s = 0.0f;
    #pragma unroll
    for (int j = 0; j < 8; j++){
        float4 hv = *(const float4*)&h[lane*4 + j*128];
        float4 wv = *(const float4*)&beta_w[lane*4 + j*128];
        s += hv.x*wv.x + hv.y*wv.y + hv.z*wv.z + hv.w*wv.w;
    }
    #pragma unroll
    for (int o = 16; o > 0; o >>= 1) s += __shfl_xor_sync(0xffffffffu, s, o);
    if (lane == 0) g_beta[gw] = sigm(s);
}

// ---------------- gated scan (writes fp32 + fp16) ----------------
__global__ void gated_scan(const float* __restrict__ latent){
    int b = blockIdx.x >> 2;
    int d = (blockIdx.x & 3) * 256 + threadIdx.x;
    float g = 0.0f;
    size_t base = (size_t)b * N_ * D_ + d;
    const float* bet = &g_beta[b * N_];
    #pragma unroll 8
    for (int n = 0; n < N_; n++){
        float a = __ldg(&bet[n]);
        g = __ldg(&latent[base + (size_t)n * D_]) + a * g;
        g_gated[base + (size_t)n * D_]  = g;
        g_gatedh[base + (size_t)n * D_] = __float2half_rn(g);
    }
}

// ---------------- V2, c2 ----------------
__global__ void v2_reduce(const float* __restrict__ w2){
    int r = blockIdx.y;
    int hcol = blockIdx.x * 256 + threadIdx.x;
    const float* p = w2 + ((size_t)DR_ + r) * H_ + hcol;
    float s = 0.0f;
    for (int d = 0; d < D_; d++) s += p[(size_t)d * R_ * H_];
    g_V2[r * H_ + hcol] = s;
}

__global__ void c2_kernel(const float* __restrict__ b2){
    int r = blockIdx.x;
    __shared__ float red[256];
    float s = 0.0f;
    for (int d = threadIdx.x; d < D_; d += 256) s += b2[DR_ + d*R_ + r];
    red[threadIdx.x] = s; __syncthreads();
    for (int o = 128; o > 0; o >>= 1){
        if (threadIdx.x < o) red[threadIdx.x] += red[threadIdx.x + o];
        __syncthreads();
    }
    if (threadIdx.x == 0) g_c2[r] = red[0];
}

// ---------------- s[t,r] ----------------
__global__ void s_kernel(){
    __shared__ float hs[H_];
    int t = blockIdx.x;
    int tid = threadIdx.x;   // 128
    for (int k = tid*4; k < H_; k += 512)
        *(float4*)&hs[k] = *(const float4*)&g_hid[(size_t)t * H_ + k];
    __syncthreads();
    int warp = tid >> 5, lane = tid & 31;
    #pragma unroll
    for (int rr = 0; rr < 4; rr++){
        int r = warp*4 + rr;
        const float* v = &g_V2[r * H_];
        float s = 0.0f;
        #pragma unroll
        for (int j = 0; j < 16; j++){
            float4 a = *(float4*)&hs[lane*4 + j*128];
            float4 w = *(const float4*)&v[lane*4 + j*128];
            s += a.x*w.x + a.y*w.y + a.z*w.z + a.w*w.w;
        }
        #pragma unroll
        for (int o = 16; o > 0; o >>= 1) s += __shfl_xor_sync(0xffffffffu, s, o);
        if (lane == 0) g_s[t*R_ + r] = s + g_c2[r];
    }
}

// ---------------- launch ----------------
extern "C" void kernel_launch(void* const* d_in, const int* in_sizes, int n_in,
                              void* d_out, int out_size)
{
    const float* latent = (const float*)d_in[0];
    const float* w_ih   = (const float*)d_in[1];
    const float* w_hh   = (const float*)d_in[2];
    const float* b_ih   = (const float*)d_in[3];
    const float* b_hh   = (const float*)d_in[4];
    const float* beta_w = (const float*)d_in[5];
    const float* dec_w1 = (const float*)d_in[6];
    const float* dec_b1 = (const float*)d_in[7];
    const float* dec_w2 = (const float*)d_in[8];
    const float* dec_b2 = (const float*)d_in[9];
    float* out = (float*)d_out;

    float*  xp;     cudaGetSymbolAddress((void**)&xp, g_xp);
    float*  hid;    cudaGetSymbolAddress((void**)&hid, g_hid);
    float*  gated;  cudaGetSymbolAddress((void**)&gated, g_gated);
    __half* w2h;    cudaGetSymbolAddress((void**)&w2h, g_w2h);
    __half* w1h;    cudaGetSymbolAddress((void**)&w1h, g_w1h);
    __half* gatedh; cudaGetSymbolAddress((void**)&gatedh, g_gatedh);
    __half* hidh;   cudaGetSymbolAddress((void**)&hidh, g_hidh);

    // fp16 weight copies
    conv_half<<<(unsigned)(((size_t)DR_*H_)/(256*8)), 256>>>(dec_w2, w2h, (size_t)DR_*H_);
    conv_half<<<(unsigned)(((size_t)H_*D_)/(256*8)),  256>>>(dec_w1, w1h, (size_t)H_*D_);

    // xp = latent @ w_ih^T + b_ih   (fp32 — feeds recurrence)
    sgemm_bias<<<dim3(G3_/BN, T_/BM), 256>>>(latent, w_ih, b_ih, xp, T_, G3_, D_);
    // GRU recurrence (persistent, warp-per-dim, proven two-level barrier)
    gru_reset<<<1, 128>>>();
    gru_kernel<<<GCTAS, 256>>>(w_hh, b_hh);
    // beta
    beta_kernel<<<T_*32/256, 256>>>(beta_w);
    // gated associative scan
    gated_scan<<<B_*4, 256>>>(latent);
    // hid = gelu(gated @ dec_w1^T + b1)  [fp16 tensor cores]
    hgemm_nt<2><<<dim3(T_/MBM, H_/MBN), 256>>>(gatedh, w1h, dec_b1, hid, hidh,
                                               T_, H_, D_, nullptr, nullptr);
    // V2, c2, s (fp32)
    v2_reduce<<<dim3(H_/256, R_), 256>>>(dec_w2);
    c2_kernel<<<R_, 256>>>(dec_b2);
    s_kernel<<<T_, 128>>>();
    // fused decoder GEMM + control + residual [fp16 tensor cores]
    hgemm_nt<3><<<dim3(T_/MBM, DR_/MBN), 256>>>(hidh, w2h, dec_b2, out, nullptr,
                                                T_, DR_, H_, latent, gated);
}

// round 12
// speedup vs baseline: 1.1218x; 1.1218x over previous
#include <cuda_runtime.h>
#include <cuda_fp16.h>
#include <math.h>
#include <stdint.h>

#define B_  2
#define N_  1024
#define D_  1024
#define R_  16
#define H_  2048
#define T_  (B_*N_)
#define G3_ (3*D_)
#define DR_ (D_*R_)

// ---------------- scratch ----------------
__device__ float g_xp[(size_t)T_*G3_];
__device__ float g_hbuf[2][B_*D_];
__device__ float g_gruout[(size_t)T_*D_];
__device__ float g_beta[T_];
__device__ float g_gated[(size_t)T_*D_];
__device__ float g_hid[(size_t)T_*H_];
__device__ float g_V2[R_*H_];
__device__ float g_c2[R_];
__device__ float g_s[T_*R_];
__device__ __half g_w2h[(size_t)DR_*H_];
__device__ __half g_w1h[(size_t)H_*D_];
__device__ __half g_gatedh[(size_t)T_*D_];
__device__ __half g_hidh[(size_t)T_*H_];
__device__ __half g_lath[(size_t)T_*D_];
__device__ __half g_wihh[(size_t)G3_*D_];

#define GCTAS 128
__device__ int g_arrive[GCTAS];
__device__ int g_gen;

// ---------------- helpers ----------------
__device__ __forceinline__ void fma2(unsigned long long &d, unsigned long long a, unsigned long long b){
    asm("fma.rn.f32x2 %0, %1, %2, %0;" : "+l"(d) : "l"(a), "l"(b));
}
__device__ __forceinline__ unsigned long long pk2(float a, float b){
    unsigned long long r;
    asm("mov.b64 %0, {%1, %2};" : "=l"(r) : "r"(__float_as_uint(a)), "r"(__float_as_uint(b)));
    return r;
}
__device__ __forceinline__ float2 un2(unsigned long long v){
    unsigned int lo, hi;
    asm("mov.b64 {%0, %1}, %2;" : "=r"(lo), "=r"(hi) : "l"(v));
    return make_float2(__uint_as_float(lo), __uint_as_float(hi));
}
__device__ __forceinline__ float4 ldcg4(const float* p){
    float4 v;
    asm volatile("ld.global.cg.v4.f32 {%0,%1,%2,%3}, [%4];"
                 : "=f"(v.x),"=f"(v.y),"=f"(v.z),"=f"(v.w) : "l"(p));
    return v;
}
__device__ __forceinline__ int4 ldvol4(const int* p){
    int4 v;
    asm volatile("ld.volatile.global.v4.s32 {%0,%1,%2,%3}, [%4];"
                 : "=r"(v.x),"=r"(v.y),"=r"(v.z),"=r"(v.w) : "l"(p));
    return v;
}
__device__ __forceinline__ uint32_t s2u(const void* p){
    return (uint32_t)__cvta_generic_to_shared(p);
}
__device__ __forceinline__ float gelu_tanh(float x){
    float c = x + 0.044715f * x * x * x;
    return 0.5f * x * (1.0f + tanhf(0.7978845608028654f * c));
}
__device__ __forceinline__ float sigm(float x){ return 1.0f / (1.0f + expf(-x)); }

// ---------------- fp32->fp16 convert ----------------
__device__ __forceinline__ void conv_body(const float* __restrict__ src, __half* __restrict__ dst, size_t i){
    float4 v0 = *(const float4*)&src[i];
    float4 v1 = *(const float4*)&src[i+4];
    __half2 h0 = __floats2half2_rn(v0.x, v0.y);
    __half2 h1 = __floats2half2_rn(v0.z, v0.w);
    __half2 h2 = __floats2half2_rn(v1.x, v1.y);
    __half2 h3 = __floats2half2_rn(v1.z, v1.w);
    uint4 o;
    o.x = *(uint32_t*)&h0; o.y = *(uint32_t*)&h1; o.z = *(uint32_t*)&h2; o.w = *(uint32_t*)&h3;
    *(uint4*)&dst[i] = o;
}
__global__ void conv_half(const float* __restrict__ src, __half* __restrict__ dst, size_t n){
    size_t i = ((size_t)blockIdx.x*256 + threadIdx.x)*8;
    if (i >= n) return;
    conv_body(src, dst, i);
}
// conv + GRU flag reset fused (block 0 also resets barrier state; gru launches later in-stream)
__global__ void conv_half_reset(const float* __restrict__ src, __half* __restrict__ dst, size_t n){
    if (blockIdx.x == 0){
        if (threadIdx.x < GCTAS) g_arrive[threadIdx.x] = 0;
        if (threadIdx.x == 0) g_gen = 0;
    }
    size_t i = ((size_t)blockIdx.x*256 + threadIdx.x)*8;
    if (i >= n) return;
    conv_body(src, dst, i);
}

// ---------------- fp16 HMMA GEMM NT: C[M,N] = A[M,K] @ Bw[N,K]^T ----------------
// EPI 1: C = acc+bias (fp32)
// EPI 2: C = gelu(acc+bias) (fp32) + half copy to Ch
// EPI 3: fused decoder: out[t,d] = latent + gated * sum_r (acc+bias)[t,d*16+r]*g_s[t,r]
#define MBM 128
#define MBN 128
#define MBK 32
#define MROW 40

template<int EPI>
__global__ __launch_bounds__(256) void hgemm_nt(
    const __half* __restrict__ Ah, const __half* __restrict__ Bh,
    const float* __restrict__ bias, float* __restrict__ C,
    __half* __restrict__ Ch,
    int M, int N, int K,
    const float* __restrict__ latent, const float* __restrict__ gated)
{
    __shared__ __align__(16) __half At[MBM*MROW];
    __shared__ __align__(16) __half Bt[MBN*MROW];
    __shared__ float ss[(EPI==3)? MBM*16 : 1];

    const int tid  = threadIdx.x;
    const int bm   = blockIdx.x, bn = blockIdx.y;
    const int lane = tid & 31, w = tid >> 5;
    const int wm   = w >> 2, wn = w & 3;
    const int g    = lane >> 2, qt = lane & 3;

    if (EPI == 3){
        for (int k = tid; k < MBM*16; k += 256)
            ss[k] = g_s[(bm*MBM + (k >> 4))*R_ + (k & 15)];
    }

    const __half* Ab = Ah + (size_t)bm * MBM * K;
    const __half* Bb = Bh + (size_t)bn * MBN * K;

    const int crow = tid >> 1;
    const int cc   = (tid & 1) * 2;

    float acc[4][4][4];
    #pragma unroll
    for (int a = 0; a < 4; a++)
        #pragma unroll
        for (int b = 0; b < 4; b++)
            #pragma unroll
            for (int c = 0; c < 4; c++) acc[a][b][c] = 0.0f;

    const int KT = K / MBK;
    uint4 ra0, ra1, rb0, rb1;
    ra0 = *(const uint4*)(Ab + (size_t)crow*K + cc*8);
    ra1 = *(const uint4*)(Ab + (size_t)crow*K + cc*8 + 8);
    rb0 = *(const uint4*)(Bb + (size_t)crow*K + cc*8);
    rb1 = *(const uint4*)(Bb + (size_t)crow*K + cc*8 + 8);
    ((uint4*)At)[crow*5 + cc] = ra0; ((uint4*)At)[crow*5 + cc + 1] = ra1;
    ((uint4*)Bt)[crow*5 + cc] = rb0; ((uint4*)Bt)[crow*5 + cc + 1] = rb1;
    __syncthreads();

    const uint32_t aBase = s2u(At), bBase = s2u(Bt);

    for (int kt = 0; kt < KT; kt++){
        if (kt + 1 < KT){
            const __half* An = Ab + (size_t)(kt+1)*MBK;
            const __half* Bn = Bb + (size_t)(kt+1)*MBK;
            ra0 = *(const uint4*)(An + (size_t)crow*K + cc*8);
            ra1 = *(const uint4*)(An + (size_t)crow*K + cc*8 + 8);
            rb0 = *(const uint4*)(Bn + (size_t)crow*K + cc*8);
            rb1 = *(const uint4*)(Bn + (size_t)crow*K + cc*8 + 8);
        }
        #pragma unroll
        for (int ks = 0; ks < 2; ks++){
            uint32_t af[4][4];
            #pragma unroll
            for (int mt = 0; mt < 4; mt++){
                int r   = wm*64 + mt*16 + (lane & 15);
                int col = ks*16 + ((lane >> 4) << 3);
                uint32_t addr = aBase + (uint32_t)(r*MROW + col)*2;
                asm volatile("ldmatrix.sync.aligned.m8n8.x4.shared.b16 {%0,%1,%2,%3},[%4];"
                    : "=r"(af[mt][0]),"=r"(af[mt][1]),"=r"(af[mt][2]),"=r"(af[mt][3]) : "r"(addr));
            }
            uint32_t bf[2][4];
            #pragma unroll
            for (int np = 0; np < 2; np++){
                int r   = wn*32 + np*16 + (lane & 7) + ((lane & 16) ? 8 : 0);
                int col = ks*16 + ((lane & 8) ? 8 : 0);
                uint32_t addr = bBase + (uint32_t)(r*MROW + col)*2;
                asm volatile("ldmatrix.sync.aligned.m8n8.x4.shared.b16 {%0,%1,%2,%3},[%4];"
                    : "=r"(bf[np][0]),"=r"(bf[np][1]),"=r"(bf[np][2]),"=r"(bf[np][3]) : "r"(addr));
            }
            #pragma unroll
            for (int mt = 0; mt < 4; mt++)
                #pragma unroll
                for (int nt = 0; nt < 4; nt++){
                    uint32_t b0 = bf[nt>>1][(nt&1)*2], b1 = bf[nt>>1][(nt&1)*2 + 1];
                    asm volatile(
                        "mma.sync.aligned.m16n8k16.row.col.f32.f16.f16.f32 "
                        "{%0,%1,%2,%3},{%4,%5,%6,%7},{%8,%9},{%0,%1,%2,%3};"
                        : "+f"(acc[mt][nt][0]),"+f"(acc[mt][nt][1]),
                          "+f"(acc[mt][nt][2]),"+f"(acc[mt][nt][3])
                        : "r"(af[mt][0]),"r"(af[mt][1]),"r"(af[mt][2]),"r"(af[mt][3]),
                          "r"(b0),"r"(b1));
                }
        }
        __syncthreads();
        if (kt + 1 < KT){
            ((uint4*)At)[crow*5 + cc] = ra0; ((uint4*)At)[crow*5 + cc + 1] = ra1;
            ((uint4*)Bt)[crow*5 + cc] = rb0; ((uint4*)Bt)[crow*5 + cc + 1] = rb1;
            __syncthreads();
        }
    }

    if (EPI == 1 || EPI == 2){
        #pragma unroll
        for (int mt = 0; mt < 4; mt++)
            #pragma unroll
            for (int nt = 0; nt < 4; nt++)
                #pragma unroll
                for (int rh = 0; rh < 2; rh++){
                    int row = bm*MBM + wm*64 + mt*16 + g + rh*8;
                    int col = bn*MBN + wn*32 + nt*8 + qt*2;
                    float2 bv = *(const float2*)&bias[col];
                    float v0 = acc[mt][nt][rh*2+0] + bv.x;
                    float v1 = acc[mt][nt][rh*2+1] + bv.y;
                    if (EPI == 2){
                        v0 = gelu_tanh(v0);
                        v1 = gelu_tanh(v1);
                        __half2 hv = __floats2half2_rn(v0, v1);
                        *(__half2*)&Ch[(size_t)row*N + col] = hv;
                    }
                    *(float2*)&C[(size_t)row*N + col] = make_float2(v0, v1);
                }
    } else {
        #pragma unroll
        for (int mt = 0; mt < 4; mt++)
            #pragma unroll
            for (int rh = 0; rh < 2; rh++){
                int lrow = wm*64 + mt*16 + g + rh*8;
                int row  = bm*MBM + lrow;
                const float* sr = &ss[lrow*16];
                #pragma unroll
                for (int np = 0; np < 2; np++){
                    float p = 0.0f;
                    #pragma unroll
                    for (int sub = 0; sub < 2; sub++){
                        int nt   = np*2 + sub;
                        int colb = bn*MBN + wn*32 + nt*8 + qt*2;
                        float2 bv = *(const float2*)&bias[colb];
                        int rr = (nt & 1)*8 + qt*2;
                        p += (acc[mt][nt][rh*2+0] + bv.x)*sr[rr]
                           + (acc[mt][nt][rh*2+1] + bv.y)*sr[rr+1];
                    }
                    p += __shfl_xor_sync(0xffffffffu, p, 1);
                    p += __shfl_xor_sync(0xffffffffu, p, 2);
                    if (qt == 0){
                        int d = bn*8 + wn*2 + np;
                        size_t idx = (size_t)row*D_ + d;
                        C[idx] = latent[idx] + gated[idx]*p;
                    }
                }
            }
    }
}

// ---------------- persistent GRU: R6 champion, verbatim ----------------
__global__ __launch_bounds__(256) void gru_kernel(const float* __restrict__ w_hh, const float* __restrict__ b_hh)
{
    __shared__ float h_s[2*D_];
    __shared__ float hp_s[48];

    const int tid = threadIdx.x, lane = tid & 31, warp = tid >> 5;
    const int bid = blockIdx.x;
    const int d0 = bid * 8;

    unsigned long long wreg[3][16];
    float bh[3];
    #pragma unroll
    for (int q = 0; q < 3; q++){
        int l = warp*3 + q;
        int grow = (l >> 3) * D_ + d0 + (l & 7);
        const float* wr = &w_hh[(size_t)grow * D_];
        #pragma unroll
        for (int j = 0; j < 8; j++){
            float4 v = *(const float4*)&wr[lane*4 + j*128];
            wreg[q][2*j]   = pk2(v.x, v.y);
            wreg[q][2*j+1] = pk2(v.z, v.w);
        }
        bh[q] = b_hh[(l >> 3) * D_ + d0 + (l & 7)];
    }

    float pxr = 0.f, pxz = 0.f, pxn = 0.f;
    const int gi = tid & 7, gb = tid >> 3;
    if (tid < 16){
        size_t xb = ((size_t)(gb*N_ + 0)) * G3_ + d0 + gi;
        pxr = g_xp[xb]; pxz = g_xp[xb + D_]; pxn = g_xp[xb + 2*D_];
    }
    __syncthreads();

    int pbuf = 0;
    for (int t = 0; t < N_; t++){
        if (t > 0){
            for (int k = tid*4; k < 2*D_; k += 1024)
                *(float4*)&h_s[k] = ldcg4(&g_hbuf[pbuf][k]);
        }
        __syncthreads();

        if (t > 0){
            #pragma unroll
            for (int q = 0; q < 3; q++){
                int l = warp*3 + q;
                unsigned long long a0 = 0ull, a1 = 0ull;
                #pragma unroll
                for (int j = 0; j < 8; j++){
                    ulonglong2 h0 = *(ulonglong2*)&h_s[lane*4 + j*128];
                    ulonglong2 h1 = *(ulonglong2*)&h_s[D_ + lane*4 + j*128];
                    fma2(a0, wreg[q][2*j],   h0.x); fma2(a0, wreg[q][2*j+1], h0.y);
                    fma2(a1, wreg[q][2*j],   h1.x); fma2(a1, wreg[q][2*j+1], h1.y);
                }
                float2 p0 = un2(a0), p1 = un2(a1);
                float s0 = p0.x + p0.y, s1 = p1.x + p1.y;
                #pragma unroll
                for (int o = 16; o > 0; o >>= 1){
                    s0 += __shfl_xor_sync(0xffffffffu, s0, o);
                    s1 += __shfl_xor_sync(0xffffffffu, s1, o);
                }
                if (lane == 0){
                    hp_s[l*2 + 0] = s0 + bh[q];
                    hp_s[l*2 + 1] = s1 + bh[q];
                }
            }
        } else {
            if (lane == 0){
                #pragma unroll
                for (int q = 0; q < 3; q++){
                    int l = warp*3 + q;
                    hp_s[l*2 + 0] = bh[q];
                    hp_s[l*2 + 1] = bh[q];
                }
            }
        }
        __syncthreads();

        if (tid < 16){
            int d = d0 + gi;
            float hr = hp_s[gi*2 + gb];
            float hz = hp_s[(8 + gi)*2 + gb];
            float hn = hp_s[(16 + gi)*2 + gb];
            float r  = sigm(pxr + hr);
            float z  = sigm(pxz + hz);
            float ng = tanhf(pxn + r*hn);
            float hprev = (t > 0) ? h_s[gb*D_ + d] : 0.0f;
            float hnew  = (1.0f - z)*ng + z*hprev;
            g_hbuf[pbuf ^ 1][gb*D_ + d] = hnew;
            g_gruout[((size_t)(gb*N_ + t)) * D_ + d] = hnew;
            __threadfence();
        }
        __syncthreads();

        if (tid == 0)
            ((volatile int*)g_arrive)[bid] = t + 1;
        if (tid < 16 && t + 1 < N_){
            size_t xb = ((size_t)(gb*N_ + t + 1)) * G3_ + d0 + gi;
            pxr = g_xp[xb]; pxz = g_xp[xb + D_]; pxn = g_xp[xb + 2*D_];
        }
        if (bid == 0 && warp == 0){
            const int* fp = &g_arrive[lane * 4];
            for (;;){
                int4 f = ldvol4(fp);
                if (f.x > t && f.y > t && f.z > t && f.w > t) break;
            }
            __syncwarp();
            if (lane == 0){
                __threadfence();
                *(volatile int*)&g_gen = t + 1;
            }
        }
        if (bid != 0 && tid == 0){
            while (*(volatile int*)&g_gen <= t) { }
        }
        __syncthreads();
        pbuf ^= 1;
    }
}

// ---------------- beta ----------------
__global__ void beta_kernel(const float* __restrict__ beta_w){
    int gw = (blockIdx.x * blockDim.x + threadIdx.x) >> 5;
    int lane = threadIdx.x & 31;
    if (gw >= T_) return;
    const float* h = &g_gruout[(size_t)gw * D_];
    float s = 0.0f;
    #pragma unroll
    for (int j = 0; j < 8; j++){
        float4 hv = *(const float4*)&h[lane*4 + j*128];
        float4 wv = *(const float4*)&beta_w[lane*4 + j*128];
        s += hv.x*wv.x + hv.y*wv.y + hv.z*wv.z + hv.w*wv.w;
    }
    #pragma unroll
    for (int o = 16; o > 0; o >>= 1) s += __shfl_xor_sync(0xffffffffu, s, o);
    if (lane == 0) g_beta[gw] = sigm(s);
}

// ---------------- gated scan (writes fp32 + fp16) ----------------
__global__ void gated_scan(const float* __restrict__ latent){
    int b = blockIdx.x >> 2;
    int d = (blockIdx.x & 3) * 256 + threadIdx.x;
    float g = 0.0f;
    size_t base = (size_t)b * N_ * D_ + d;
    const float* bet = &g_beta[b * N_];
    #pragma unroll 8
    for (int n = 0; n < N_; n++){
        float a = __ldg(&bet[n]);
        g = __ldg(&latent[base + (size_t)n * D_]) + a * g;
        g_gated[base + (size_t)n * D_]  = g;
        g_gatedh[base + (size_t)n * D_] = __float2half_rn(g);
    }
}

// ---------------- V2, c2 ----------------
__global__ void v2_reduce(const float* __restrict__ w2){
    int r = blockIdx.y;
    int hcol = blockIdx.x * 256 + threadIdx.x;
    const float* p = w2 + ((size_t)DR_ + r) * H_ + hcol;
    float s = 0.0f;
    for (int d = 0; d < D_; d++) s += p[(size_t)d * R_ * H_];
    g_V2[r * H_ + hcol] = s;
}

__global__ void c2_kernel(const float* __restrict__ b2){
    int r = blockIdx.x;
    __shared__ float red[256];
    float s = 0.0f;
    for (int d = threadIdx.x; d < D_; d += 256) s += b2[DR_ + d*R_ + r];
    red[threadIdx.x] = s; __syncthreads();
    for (int o = 128; o > 0; o >>= 1){
        if (threadIdx.x < o) red[threadIdx.x] += red[threadIdx.x + o];
        __syncthreads();
    }
    if (threadIdx.x == 0) g_c2[r] = red[0];
}

// ---------------- s[t,r] ----------------
__global__ void s_kernel(){
    __shared__ float hs[H_];
    int t = blockIdx.x;
    int tid = threadIdx.x;   // 128
    for (int k = tid*4; k < H_; k += 512)
        *(float4*)&hs[k] = *(const float4*)&g_hid[(size_t)t * H_ + k];
    __syncthreads();
    int warp = tid >> 5, lane = tid & 31;
    #pragma unroll
    for (int rr = 0; rr < 4; rr++){
        int r = warp*4 + rr;
        const float* v = &g_V2[r * H_];
        float s = 0.0f;
        #pragma unroll
        for (int j = 0; j < 16; j++){
            float4 a = *(float4*)&hs[lane*4 + j*128];
            float4 w = *(const float4*)&v[lane*4 + j*128];
            s += a.x*w.x + a.y*w.y + a.z*w.z + a.w*w.w;
        }
        #pragma unroll
        for (int o = 16; o > 0; o >>= 1) s += __shfl_xor_sync(0xffffffffu, s, o);
        if (lane == 0) g_s[t*R_ + r] = s + g_c2[r];
    }
}

// ---------------- launch ----------------
extern "C" void kernel_launch(void* const* d_in, const int* in_sizes, int n_in,
                              void* d_out, int out_size)
{
    const float* latent = (const float*)d_in[0];
    const float* w_ih   = (const float*)d_in[1];
    const float* w_hh   = (const float*)d_in[2];
    const float* b_ih   = (const float*)d_in[3];
    const float* b_hh   = (const float*)d_in[4];
    const float* beta_w = (const float*)d_in[5];
    const float* dec_w1 = (const float*)d_in[6];
    const float* dec_b1 = (const float*)d_in[7];
    const float* dec_w2 = (const float*)d_in[8];
    const float* dec_b2 = (const float*)d_in[9];
    float* out = (float*)d_out;

    float*  xp;     cudaGetSymbolAddress((void**)&xp, g_xp);
    float*  hid;    cudaGetSymbolAddress((void**)&hid, g_hid);
    float*  gated;  cudaGetSymbolAddress((void**)&gated, g_gated);
    __half* w2h;    cudaGetSymbolAddress((void**)&w2h, g_w2h);
    __half* w1h;    cudaGetSymbolAddress((void**)&w1h, g_w1h);
    __half* gatedh; cudaGetSymbolAddress((void**)&gatedh, g_gatedh);
    __half* hidh;   cudaGetSymbolAddress((void**)&hidh, g_hidh);
    __half* lath;   cudaGetSymbolAddress((void**)&lath, g_lath);
    __half* wihh;   cudaGetSymbolAddress((void**)&wihh, g_wihh);

    // idx 0: latent -> fp16
    conv_half<<<(unsigned)(((size_t)T_*D_)/(256*8)), 256>>>(latent, lath, (size_t)T_*D_);
    // idx 1: w_ih -> fp16, + GRU barrier reset fused into block 0
    conv_half_reset<<<(unsigned)(((size_t)G3_*D_)/(256*8)), 256>>>(w_ih, wihh, (size_t)G3_*D_);
    // idx 2: xp = latent @ w_ih^T + b_ih  [fp16 TC, fp32 out]
    hgemm_nt<1><<<dim3(T_/MBM, G3_/MBN), 256>>>(lath, wihh, b_ih, xp, nullptr,
                                                T_, G3_, D_, nullptr, nullptr);
    // idx 3: GRU recurrence (profiler lands here)
    gru_kernel<<<GCTAS, 256>>>(w_hh, b_hh);
    // beta
    beta_kernel<<<T_*32/256, 256>>>(beta_w);
    // gated associative scan
    gated_scan<<<B_*4, 256>>>(latent);
    // dec_w1 -> fp16
    conv_half<<<(unsigned)(((size_t)H_*D_)/(256*8)), 256>>>(dec_w1, w1h, (size_t)H_*D_);
    // hid = gelu(gated @ dec_w1^T + b1)  [fp16 TC]
    hgemm_nt<2><<<dim3(T_/MBM, H_/MBN), 256>>>(gatedh, w1h, dec_b1, hid, hidh,
                                               T_, H_, D_, nullptr, nullptr);
    // dec_w2 -> fp16
    conv_half<<<(unsigned)(((size_t)DR_*H_)/(256*8)), 256>>>(dec_w2, w2h, (size_t)DR_*H_);
    // V2, c2, s (fp32)
    v2_reduce<<<dim3(H_/256, R_), 256>>>(dec_w2);
    c2_kernel<<<R_, 256>>>(dec_b2);
    s_kernel<<<T_, 128>>>();
    // fused decoder GEMM + control + residual [fp16 TC]
    hgemm_nt<3><<<dim3(T_/MBM, DR_/MBN), 256>>>(hidh, w2h, dec_b2, out, nullptr,
                                                T_, DR_, H_, latent, gated);
}